// round 3
// baseline (speedup 1.0000x reference)
#include <cuda_runtime.h>
#include <math.h>

// Problem dims (fixed by the dataset)
#define B_ROWS 65536
#define D_IN   784
#define H_DIM  512
#define D_OUT  10
#define KCODE  512
#define BN_EPS 1e-5f

// ---------------- scratch (static device globals; no allocations) ----------------
__device__ float g_qW1[H_DIM * D_IN];
__device__ float g_qW2[H_DIM * H_DIM];
__device__ float g_h1[(size_t)B_ROWS * H_DIM];
__device__ float g_h2[(size_t)B_ROWS * H_DIM];
__device__ float g_colsum[H_DIM];
__device__ float g_colsumsq[H_DIM];
__device__ float g_s[H_DIM];
__device__ float g_t[H_DIM];
__device__ float g_diff1;
__device__ float g_diff2;

// ---------------- zero accumulators ----------------
__global__ void zero_accums() {
    int t = threadIdx.x;
    if (t < H_DIM) { g_colsum[t] = 0.f; g_colsumsq[t] = 0.f; }
    if (t == 0) { g_diff1 = 0.f; g_diff2 = 0.f; }
}

// Reference-replicating fp32 helpers (no contraction allowed)
__device__ __forceinline__ float sq_sum_seq(const float* v, int n) {
    // matches (x*x).sum(): rounded multiply, then sequential adds ascending
    float s = __fmul_rn(v[0], v[0]);
    for (int d = 1; d < n; d++) s = __fadd_rn(s, __fmul_rn(v[d], v[d]));
    return s;
}

// ---------------- VQ quantize W1: blocks of (in_mem=7, out_mem=4), dim 28 ----------------
// dist = (|v|^2 - 2*(v@e)) + |e|^2, each piece evaluated in reference fp32 order.
// 4 lanes cooperate per VQ block, interleaved codeword partition.
__global__ void quant_w1(const float* __restrict__ W1, const float* __restrict__ E1) {
    extern __shared__ float smem[];
    float* sE  = smem;               // [KCODE][28] exact codewords, codeword-major
    float* sSe = smem + KCODE * 28;  // [KCODE] |e|^2 in reference order

    for (int i = threadIdx.x; i < KCODE * 28; i += 128) {
        int k = i / 28, d = i % 28;
        sE[k * 28 + d] = E1[d * KCODE + k];
    }
    __syncthreads();
    for (int k = threadIdx.x; k < KCODE; k += 128)
        sSe[k] = sq_sum_seq(sE + k * 28, 28);
    __syncthreads();

    int gid = blockIdx.x * 128 + threadIdx.x;
    int blk = gid >> 2;      // 0..14335  (128 out_g * 112 in_g)
    int sub = gid & 3;
    int og = blk / 112;
    int ig = blk - og * 112;

    float v[28];
#pragma unroll
    for (int im = 0; im < 7; im++)
#pragma unroll
        for (int om = 0; om < 4; om++)
            v[im * 4 + om] = W1[(og * 4 + om) * D_IN + ig * 7 + im];
    float Sv = sq_sum_seq(v, 28);

    float best = 3.402823e38f;
    int bi = 0x7fffffff;
    for (int i = 0; i < 128; i++) {
        int k = (i << 2) | sub;
        const float* e = sE + k * 28;
        // cublas-style fma chain, ascending k-dim
        float dot = 0.f;
#pragma unroll
        for (int d = 0; d < 28; d++) dot = __fmaf_rn(v[d], e[d], dot);
        float dist = __fadd_rn(__fsub_rn(Sv, __fmul_rn(2.0f, dot)), sSe[k]);
        if (dist < best) { best = dist; bi = k; }
    }
    // reduce across the 4 lanes (argmin with lowest-index tie-break)
#pragma unroll
    for (int off = 2; off >= 1; off >>= 1) {
        float ob = __shfl_down_sync(0xffffffffu, best, off);
        int   oi = __shfl_down_sync(0xffffffffu, bi, off);
        if (ob < best || (ob == best && oi < bi)) { best = ob; bi = oi; }
    }
    if (sub == 0) {
        const float* e = sE + bi * 28;
        float dsum = 0.f;
#pragma unroll
        for (int im = 0; im < 7; im++)
#pragma unroll
            for (int om = 0; om < 4; om++) {
                int d = im * 4 + om;
                float q = e[d];
                g_qW1[(og * 4 + om) * D_IN + ig * 7 + im] = q;
                float df = q - v[d];
                dsum = fmaf(df, df, dsum);
            }
        atomicAdd(&g_diff1, dsum);
    }
}

// ---------------- VQ quantize W2: blocks of (in_mem=16, out_mem=1), dim 16 ----------------
__global__ void quant_w2(const float* __restrict__ W2, const float* __restrict__ E2) {
    __shared__ float sE[KCODE * 17];  // padded stride 17, exact codewords
    __shared__ float sSe[KCODE];
    for (int i = threadIdx.x; i < KCODE * 16; i += 128) {
        int k = i >> 4, d = i & 15;
        sE[k * 17 + d] = E2[d * KCODE + k];
    }
    __syncthreads();
    for (int k = threadIdx.x; k < KCODE; k += 128) {
        const float* e = sE + k * 17;
        float s = __fmul_rn(e[0], e[0]);
        for (int d = 1; d < 16; d++) s = __fadd_rn(s, __fmul_rn(e[d], e[d]));
        sSe[k] = s;
    }
    __syncthreads();

    int gid = blockIdx.x * 128 + threadIdx.x;
    int blk = gid >> 2;      // 0..16383  (512 out_g * 32 in_g)
    int sub = gid & 3;
    int og = blk >> 5;
    int ig = blk & 31;

    float v[16];
    const float4* wp = (const float4*)(W2 + og * H_DIM + ig * 16);
#pragma unroll
    for (int q4 = 0; q4 < 4; q4++) {
        float4 w = wp[q4];
        v[q4 * 4 + 0] = w.x; v[q4 * 4 + 1] = w.y; v[q4 * 4 + 2] = w.z; v[q4 * 4 + 3] = w.w;
    }
    float Sv = sq_sum_seq(v, 16);

    float best = 3.402823e38f;
    int bi = 0x7fffffff;
    for (int i = 0; i < 128; i++) {
        int k = (i << 2) | sub;
        const float* e = sE + k * 17;
        float dot = 0.f;
#pragma unroll
        for (int d = 0; d < 16; d++) dot = __fmaf_rn(v[d], e[d], dot);
        float dist = __fadd_rn(__fsub_rn(Sv, __fmul_rn(2.0f, dot)), sSe[k]);
        if (dist < best) { best = dist; bi = k; }
    }
#pragma unroll
    for (int off = 2; off >= 1; off >>= 1) {
        float ob = __shfl_down_sync(0xffffffffu, best, off);
        int   oi = __shfl_down_sync(0xffffffffu, bi, off);
        if (ob < best || (ob == best && oi < bi)) { best = ob; bi = oi; }
    }
    if (sub == 0) {
        const float* e = sE + bi * 17;
        float dsum = 0.f;
#pragma unroll
        for (int d = 0; d < 16; d++) {
            float q = e[d];
            g_qW2[og * H_DIM + ig * 16 + d] = q;
            float df = q - v[d];
            dsum = fmaf(df, df, dsum);
        }
        atomicAdd(&g_diff2, dsum);
    }
}

// ---------------- SGEMM: C[M,N] = relu(f(A)[M,K] * B[N,K]^T + bias[N]) ----------------
// f(A) = fma(A, s[k], t[k]) if USE_BN (BN materialized pre-GEMM, matching bn(h) @ qW2^T).
// 128x128x16 tiles, 256 threads, 8x8 per thread, double-buffered SMEM. Exact fp32.
#define BM 128
#define BN 128
#define BK 16

template <int USE_BN>
__global__ __launch_bounds__(256) void sgemm_relu(
    const float* __restrict__ A, const float* __restrict__ Bmat,
    const float* __restrict__ bias, float* __restrict__ C,
    const float* __restrict__ sv, const float* __restrict__ tv,
    int M, int N, int K)
{
    __shared__ __align__(16) float As[2][BK][BM];
    __shared__ __align__(16) float Bs[2][BK][BN];

    const int tid = threadIdx.x;
    const int bm = blockIdx.y * BM;
    const int bn = blockIdx.x * BN;
    const int tx = tid & 15, ty = tid >> 4;

    const int lr = tid >> 1;          // 0..127 (row within tile)
    const int lc = (tid & 1) * 8;     // 0 or 8 (k offset within tile)

    const float* Aptr = A + (size_t)(bm + lr) * K + lc;
    const float* Bptr = Bmat + (size_t)(bn + lr) * K + lc;

    float4 ra0 = *(const float4*)(Aptr + 0);
    float4 ra1 = *(const float4*)(Aptr + 4);
    float4 rb0 = *(const float4*)(Bptr + 0);
    float4 rb1 = *(const float4*)(Bptr + 4);

#define XFA(val, q, kb) (USE_BN ? __fmaf_rn((val), __ldg(sv + (kb) + lc + (q)), __ldg(tv + (kb) + lc + (q))) : (val))
#define STORE_TILE(b, kb)                                                              \
    do {                                                                               \
        As[b][lc + 0][lr] = XFA(ra0.x, 0, kb); As[b][lc + 1][lr] = XFA(ra0.y, 1, kb);  \
        As[b][lc + 2][lr] = XFA(ra0.z, 2, kb); As[b][lc + 3][lr] = XFA(ra0.w, 3, kb);  \
        As[b][lc + 4][lr] = XFA(ra1.x, 4, kb); As[b][lc + 5][lr] = XFA(ra1.y, 5, kb);  \
        As[b][lc + 6][lr] = XFA(ra1.z, 6, kb); As[b][lc + 7][lr] = XFA(ra1.w, 7, kb);  \
        Bs[b][lc + 0][lr] = rb0.x; Bs[b][lc + 1][lr] = rb0.y;                          \
        Bs[b][lc + 2][lr] = rb0.z; Bs[b][lc + 3][lr] = rb0.w;                          \
        Bs[b][lc + 4][lr] = rb1.x; Bs[b][lc + 5][lr] = rb1.y;                          \
        Bs[b][lc + 6][lr] = rb1.z; Bs[b][lc + 7][lr] = rb1.w;                          \
    } while (0)

    float acc[8][8];
#pragma unroll
    for (int i = 0; i < 8; i++)
#pragma unroll
        for (int j = 0; j < 8; j++) acc[i][j] = 0.f;

    const int KT = K / BK;
    int buf = 0;
    STORE_TILE(0, 0);
    __syncthreads();

    for (int kt = 0; kt < KT; kt++) {
        if (kt + 1 < KT) {
            const float* Ap = Aptr + (size_t)(kt + 1) * BK;
            const float* Bp = Bptr + (size_t)(kt + 1) * BK;
            ra0 = *(const float4*)Ap;       ra1 = *(const float4*)(Ap + 4);
            rb0 = *(const float4*)Bp;       rb1 = *(const float4*)(Bp + 4);
        }
#pragma unroll
        for (int kk = 0; kk < BK; kk++) {
            float4 a0 = *(const float4*)&As[buf][kk][ty * 8];
            float4 a1 = *(const float4*)&As[buf][kk][ty * 8 + 4];
            float4 b0 = *(const float4*)&Bs[buf][kk][tx * 8];
            float4 b1 = *(const float4*)&Bs[buf][kk][tx * 8 + 4];
            float av[8] = {a0.x, a0.y, a0.z, a0.w, a1.x, a1.y, a1.z, a1.w};
            float bv[8] = {b0.x, b0.y, b0.z, b0.w, b1.x, b1.y, b1.z, b1.w};
#pragma unroll
            for (int i = 0; i < 8; i++)
#pragma unroll
                for (int j = 0; j < 8; j++)
                    acc[i][j] = fmaf(av[i], bv[j], acc[i][j]);
        }
        if (kt + 1 < KT) {
            buf ^= 1;
            STORE_TILE(buf, (kt + 1) * BK);
            __syncthreads();
        }
    }

    // epilogue: bias + relu, vectorized stores
    const int cb = bn + tx * 8;
    float bb[8];
#pragma unroll
    for (int j = 0; j < 8; j++) bb[j] = __ldg(&bias[cb + j]);
#pragma unroll
    for (int i = 0; i < 8; i++) {
        float* cp = C + (size_t)(bm + ty * 8 + i) * N + cb;
        float4 o0, o1;
        o0.x = fmaxf(acc[i][0] + bb[0], 0.f);
        o0.y = fmaxf(acc[i][1] + bb[1], 0.f);
        o0.z = fmaxf(acc[i][2] + bb[2], 0.f);
        o0.w = fmaxf(acc[i][3] + bb[3], 0.f);
        o1.x = fmaxf(acc[i][4] + bb[4], 0.f);
        o1.y = fmaxf(acc[i][5] + bb[5], 0.f);
        o1.z = fmaxf(acc[i][6] + bb[6], 0.f);
        o1.w = fmaxf(acc[i][7] + bb[7], 0.f);
        *(float4*)(cp + 0) = o0;
        *(float4*)(cp + 4) = o1;
    }
#undef XFA
#undef STORE_TILE
}

// ---------------- per-column sum / sumsq over h1 ----------------
__global__ void colstats(const float* __restrict__ h) {
    int col = (blockIdx.x << 7) | (threadIdx.x & 127);
    int r0 = blockIdx.y * 512;
    float s = 0.f, s2 = 0.f;
#pragma unroll 4
    for (int r = 0; r < 512; r++) {
        float v = h[(size_t)(r0 + r) * H_DIM + col];
        s += v;
        s2 = fmaf(v, v, s2);
    }
    atomicAdd(&g_colsum[col], s);
    atomicAdd(&g_colsumsq[col], s2);
}

// ---------------- BN scale/shift ----------------
__global__ void finalize_stats(const float* __restrict__ gamma, const float* __restrict__ beta) {
    int j = threadIdx.x;
    if (j < H_DIM) {
        float mu = g_colsum[j] * (1.f / (float)B_ROWS);
        float var = g_colsumsq[j] * (1.f / (float)B_ROWS) - mu * mu;
        float s = gamma[j] * (1.0f / sqrtf(var + BN_EPS));
        g_s[j] = s;
        g_t[j] = beta[j] - mu * s;
    }
}

// ---------------- GEMM3: out[B,10] = h2 @ W3^T + b3 (warp per row), exact fp32 ----------------
__global__ void gemm3(const float* __restrict__ h2, const float* __restrict__ W3,
                      const float* __restrict__ b3, float* __restrict__ out) {
    int gwarp = (blockIdx.x * blockDim.x + threadIdx.x) >> 5;
    int lane = threadIdx.x & 31;
    const float4* hv = (const float4*)(h2 + (size_t)gwarp * H_DIM);
    float acc[10];
#pragma unroll
    for (int j = 0; j < 10; j++) acc[j] = 0.f;
#pragma unroll
    for (int c4 = 0; c4 < 4; c4++) {
        int c = lane + 32 * c4;
        float4 h4 = hv[c];
        int k = c << 2;
#pragma unroll
        for (int j = 0; j < 10; j++) {
            float4 w4 = __ldg((const float4*)(W3 + j * H_DIM + k));
            float a = fmaf(h4.x, w4.x, 0.f);
            a = fmaf(h4.y, w4.y, a);
            a = fmaf(h4.z, w4.z, a);
            a = fmaf(h4.w, w4.w, a);
            acc[j] += a;
        }
    }
#pragma unroll
    for (int j = 0; j < 10; j++)
#pragma unroll
        for (int off = 16; off; off >>= 1)
            acc[j] += __shfl_down_sync(0xffffffffu, acc[j], off);
    if (lane == 0) {
#pragma unroll
        for (int j = 0; j < 10; j++)
            out[(size_t)gwarp * D_OUT + j] = acc[j] + __ldg(&b3[j]);
    }
}

// ---------------- diff scalar ----------------
__global__ void write_diff(float* __restrict__ out, int out_size) {
    if (out_size > B_ROWS * D_OUT)
        out[out_size - 1] = g_diff1 * (1.f / (float)(H_DIM * D_IN)) +
                            g_diff2 * (1.f / (float)(H_DIM * H_DIM));
}

// ---------------- launcher ----------------
extern "C" void kernel_launch(void* const* d_in, const int* in_sizes, int n_in,
                              void* d_out, int out_size) {
    const float* x      = (const float*)d_in[0];
    const float* W1     = (const float*)d_in[1];
    const float* b1     = (const float*)d_in[2];
    const float* gamma1 = (const float*)d_in[3];
    const float* beta1  = (const float*)d_in[4];
    const float* E1     = (const float*)d_in[5];
    const float* W2     = (const float*)d_in[6];
    const float* b2     = (const float*)d_in[7];
    const float* E2     = (const float*)d_in[8];
    const float* W3     = (const float*)d_in[9];
    const float* b3     = (const float*)d_in[10];
    float* out = (float*)d_out;

    (void)in_sizes; (void)n_in;

    // quant_w1 needs (512*28 + 512)*4 = 59392 bytes dynamic smem
    cudaFuncSetAttribute(quant_w1, cudaFuncAttributeMaxDynamicSharedMemorySize, 59392);

    float *qW1p, *qW2p, *h1p, *h2p, *sp, *tp;
    cudaGetSymbolAddress((void**)&qW1p, g_qW1);
    cudaGetSymbolAddress((void**)&qW2p, g_qW2);
    cudaGetSymbolAddress((void**)&h1p, g_h1);
    cudaGetSymbolAddress((void**)&h2p, g_h2);
    cudaGetSymbolAddress((void**)&sp, g_s);
    cudaGetSymbolAddress((void**)&tp, g_t);

    zero_accums<<<1, 512>>>();
    quant_w1<<<448, 128, (KCODE * 28 + KCODE) * sizeof(float)>>>(W1, E1);
    quant_w2<<<512, 128>>>(W2, E2);

    // h1 = relu(x @ qW1^T + b1)
    sgemm_relu<0><<<dim3(H_DIM / BN, B_ROWS / BM), 256>>>(
        x, qW1p, b1, h1p, nullptr, nullptr, B_ROWS, H_DIM, D_IN);

    colstats<<<dim3(H_DIM / 128, B_ROWS / 512), 128>>>(h1p);
    finalize_stats<<<1, 512>>>(gamma1, beta1);

    // h2 = relu(bn(h1) @ qW2^T + b2)  — BN applied on the A-load path
    sgemm_relu<1><<<dim3(H_DIM / BN, B_ROWS / BM), 256>>>(
        h1p, qW2p, b2, h2p, sp, tp, B_ROWS, H_DIM, H_DIM);

    // out = h2 @ W3^T + b3
    gemm3<<<B_ROWS / 8, 256>>>(h2p, W3, b3, out);

    write_diff<<<1, 1>>>(out, out_size);
}

// round 5
// speedup vs baseline: 1.8832x; 1.8832x over previous
#include <cuda_runtime.h>
#include <cuda_bf16.h>
#include <cstdint>
#include <math.h>

// Problem dims (fixed by the dataset)
#define B_ROWS 65536
#define D_IN   784
#define H_DIM  512
#define D_OUT  10
#define KCODE  512
#define BN_EPS 1e-5f

// ---------------- scratch (static device globals; no allocations) ----------------
__device__ float g_qW1[H_DIM * D_IN];
__device__ float g_qW2[H_DIM * H_DIM];
__device__ float g_h1[(size_t)B_ROWS * H_DIM];
__device__ float g_h2[(size_t)B_ROWS * H_DIM];
__device__ float g_colsum[H_DIM];
__device__ float g_colsumsq[H_DIM];
__device__ float g_s[H_DIM];
__device__ float g_t[H_DIM];
__device__ float g_diff1;
__device__ float g_diff2;

// ---------------- zero accumulators ----------------
__global__ void zero_accums() {
    int t = threadIdx.x;
    if (t < H_DIM) { g_colsum[t] = 0.f; g_colsumsq[t] = 0.f; }
    if (t == 0) { g_diff1 = 0.f; g_diff2 = 0.f; }
}

// Reference-replicating fp32 helpers (no contraction allowed)
__device__ __forceinline__ float sq_sum_seq(const float* v, int n) {
    float s = __fmul_rn(v[0], v[0]);
    for (int d = 1; d < n; d++) s = __fadd_rn(s, __fmul_rn(v[d], v[d]));
    return s;
}

// ---------------- VQ quantize W1 (unchanged from passing R3) ----------------
__global__ void quant_w1(const float* __restrict__ W1, const float* __restrict__ E1) {
    extern __shared__ float smemq[];
    float* sE  = smemq;
    float* sSe = smemq + KCODE * 28;

    for (int i = threadIdx.x; i < KCODE * 28; i += 128) {
        int k = i / 28, d = i % 28;
        sE[k * 28 + d] = E1[d * KCODE + k];
    }
    __syncthreads();
    for (int k = threadIdx.x; k < KCODE; k += 128)
        sSe[k] = sq_sum_seq(sE + k * 28, 28);
    __syncthreads();

    int gid = blockIdx.x * 128 + threadIdx.x;
    int blk = gid >> 2;
    int sub = gid & 3;
    int og = blk / 112;
    int ig = blk - og * 112;

    float v[28];
#pragma unroll
    for (int im = 0; im < 7; im++)
#pragma unroll
        for (int om = 0; om < 4; om++)
            v[im * 4 + om] = W1[(og * 4 + om) * D_IN + ig * 7 + im];
    float Sv = sq_sum_seq(v, 28);

    float best = 3.402823e38f;
    int bi = 0x7fffffff;
    for (int i = 0; i < 128; i++) {
        int k = (i << 2) | sub;
        const float* e = sE + k * 28;
        float dot = 0.f;
#pragma unroll
        for (int d = 0; d < 28; d++) dot = __fmaf_rn(v[d], e[d], dot);
        float dist = __fadd_rn(__fsub_rn(Sv, __fmul_rn(2.0f, dot)), sSe[k]);
        if (dist < best) { best = dist; bi = k; }
    }
#pragma unroll
    for (int off = 2; off >= 1; off >>= 1) {
        float ob = __shfl_down_sync(0xffffffffu, best, off);
        int   oi = __shfl_down_sync(0xffffffffu, bi, off);
        if (ob < best || (ob == best && oi < bi)) { best = ob; bi = oi; }
    }
    if (sub == 0) {
        const float* e = sE + bi * 28;
        float dsum = 0.f;
#pragma unroll
        for (int im = 0; im < 7; im++)
#pragma unroll
            for (int om = 0; om < 4; om++) {
                int d = im * 4 + om;
                float q = e[d];
                g_qW1[(og * 4 + om) * D_IN + ig * 7 + im] = q;
                float df = q - v[d];
                dsum = fmaf(df, df, dsum);
            }
        atomicAdd(&g_diff1, dsum);
    }
}

// ---------------- VQ quantize W2 (unchanged from passing R3) ----------------
__global__ void quant_w2(const float* __restrict__ W2, const float* __restrict__ E2) {
    __shared__ float sE[KCODE * 17];
    __shared__ float sSe[KCODE];
    for (int i = threadIdx.x; i < KCODE * 16; i += 128) {
        int k = i >> 4, d = i & 15;
        sE[k * 17 + d] = E2[d * KCODE + k];
    }
    __syncthreads();
    for (int k = threadIdx.x; k < KCODE; k += 128) {
        const float* e = sE + k * 17;
        float s = __fmul_rn(e[0], e[0]);
        for (int d = 1; d < 16; d++) s = __fadd_rn(s, __fmul_rn(e[d], e[d]));
        sSe[k] = s;
    }
    __syncthreads();

    int gid = blockIdx.x * 128 + threadIdx.x;
    int blk = gid >> 2;
    int sub = gid & 3;
    int og = blk >> 5;
    int ig = blk & 31;

    float v[16];
    const float4* wp = (const float4*)(W2 + og * H_DIM + ig * 16);
#pragma unroll
    for (int q4 = 0; q4 < 4; q4++) {
        float4 w = wp[q4];
        v[q4 * 4 + 0] = w.x; v[q4 * 4 + 1] = w.y; v[q4 * 4 + 2] = w.z; v[q4 * 4 + 3] = w.w;
    }
    float Sv = sq_sum_seq(v, 16);

    float best = 3.402823e38f;
    int bi = 0x7fffffff;
    for (int i = 0; i < 128; i++) {
        int k = (i << 2) | sub;
        const float* e = sE + k * 17;
        float dot = 0.f;
#pragma unroll
        for (int d = 0; d < 16; d++) dot = __fmaf_rn(v[d], e[d], dot);
        float dist = __fadd_rn(__fsub_rn(Sv, __fmul_rn(2.0f, dot)), sSe[k]);
        if (dist < best) { best = dist; bi = k; }
    }
#pragma unroll
    for (int off = 2; off >= 1; off >>= 1) {
        float ob = __shfl_down_sync(0xffffffffu, best, off);
        int   oi = __shfl_down_sync(0xffffffffu, bi, off);
        if (ob < best || (ob == best && oi < bi)) { best = ob; bi = oi; }
    }
    if (sub == 0) {
        const float* e = sE + bi * 17;
        float dsum = 0.f;
#pragma unroll
        for (int d = 0; d < 16; d++) {
            float q = e[d];
            g_qW2[og * H_DIM + ig * 16 + d] = q;
            float df = q - v[d];
            dsum = fmaf(df, df, dsum);
        }
        atomicAdd(&g_diff2, dsum);
    }
}

// ---------------- bf16x3 tensor-core GEMM via mma.sync ----------------
// C[M,512] = relu(f(A)[M,K] @ B[512,K]^T + bias), f(A)=fma(A,s,t) if USE_BN.
// 128x128 CTA tile, BK=16, 8 warps (warp tile 32x64), hi/lo bf16 split, 3 HMMA passes.
#define TILE_SZ   6144         // 128 rows * 48 bytes (16 halves padded to 24)
#define SM_TILES0 4096         // after sv/tv vectors
#define GSMEM     (SM_TILES0 + 8 * TILE_SZ)   // 53248

__device__ __forceinline__ uint32_t pack_bf16(float lo_elem, float hi_elem) {
    __nv_bfloat162 h = __floats2bfloat162_rn(lo_elem, hi_elem);  // .x = first (low 16 bits)
    return *(uint32_t*)&h;
}

__device__ __forceinline__ void mma_bf16(float* d, const uint32_t* a, const uint32_t* b) {
    asm volatile(
        "mma.sync.aligned.m16n8k16.row.col.f32.bf16.bf16.f32 "
        "{%0,%1,%2,%3}, {%4,%5,%6,%7}, {%8,%9}, {%0,%1,%2,%3};"
        : "+f"(d[0]), "+f"(d[1]), "+f"(d[2]), "+f"(d[3])
        : "r"(a[0]), "r"(a[1]), "r"(a[2]), "r"(a[3]), "r"(b[0]), "r"(b[1]));
}

template <int USE_BN>
__global__ __launch_bounds__(256) void mma_gemm_relu(
    const float* __restrict__ A, const float* __restrict__ Bmat,
    const float* __restrict__ bias, float* __restrict__ C,
    const float* __restrict__ sv, const float* __restrict__ tv, int K)
{
    extern __shared__ char sm[];
    float* ssv = (float*)sm;
    float* stv = ssv + 512;
    char* tiles = sm + SM_TILES0;
    // tile(buf, which): which 0=Ahi 1=Alo 2=Bhi 3=Blo

    const int tid = threadIdx.x;
    const int wid = tid >> 5, lane = tid & 31;
    const int bm = blockIdx.y * 128;
    const int bn = blockIdx.x * 128;

    if (USE_BN) {
        for (int i = tid; i < H_DIM; i += 256) { ssv[i] = sv[i]; stv[i] = tv[i]; }
    }

    // gmem staging: thread loads 8 consecutive floats of one row (A and B)
    const int row = tid >> 1;            // 0..127
    const int colbase = (tid & 1) * 8;   // 0 or 8
    const float* Ap = A + (size_t)(bm + row) * K + colbase;
    const float* Bp = Bmat + (size_t)(bn + row) * K + colbase;

    float4 stA0, stA1, stB0, stB1;
    const int nkt = K / 16;

    // convert+store staged registers into tile buffer `buf` (k-tile kt for BN index)
    auto store_tile = [&](int buf, int kt) {
        char* tAhi = tiles + (buf * 4 + 0) * TILE_SZ;
        char* tAlo = tiles + (buf * 4 + 1) * TILE_SZ;
        char* tBhi = tiles + (buf * 4 + 2) * TILE_SZ;
        char* tBlo = tiles + (buf * 4 + 3) * TILE_SZ;
        float a[8] = {stA0.x, stA0.y, stA0.z, stA0.w, stA1.x, stA1.y, stA1.z, stA1.w};
        float b[8] = {stB0.x, stB0.y, stB0.z, stB0.w, stB1.x, stB1.y, stB1.z, stB1.w};
        if (USE_BN) {
            int gk = kt * 16 + colbase;
#pragma unroll
            for (int j = 0; j < 8; j++) a[j] = __fmaf_rn(a[j], ssv[gk + j], stv[gk + j]);
        }
        uint32_t off = (uint32_t)(row * 48 + colbase * 2);
#pragma unroll
        for (int p = 0; p < 2; p++) {   // pairs of 4 values -> 2 u32 each
            float ah[4], al[4], bh[4], bl[4];
#pragma unroll
            for (int j = 0; j < 4; j++) {
                float x = a[p * 4 + j];
                float fh = __bfloat162float(__float2bfloat16_rn(x));
                ah[j] = fh; al[j] = __fsub_rn(x, fh);
                x = b[p * 4 + j];
                fh = __bfloat162float(__float2bfloat16_rn(x));
                bh[j] = fh; bl[j] = __fsub_rn(x, fh);
            }
            uint32_t o = off + p * 8;
            *(uint32_t*)(tAhi + o)     = pack_bf16(ah[0], ah[1]);
            *(uint32_t*)(tAhi + o + 4) = pack_bf16(ah[2], ah[3]);
            *(uint32_t*)(tAlo + o)     = pack_bf16(al[0], al[1]);
            *(uint32_t*)(tAlo + o + 4) = pack_bf16(al[2], al[3]);
            *(uint32_t*)(tBhi + o)     = pack_bf16(bh[0], bh[1]);
            *(uint32_t*)(tBhi + o + 4) = pack_bf16(bh[2], bh[3]);
            *(uint32_t*)(tBlo + o)     = pack_bf16(bl[0], bl[1]);
            *(uint32_t*)(tBlo + o + 4) = pack_bf16(bl[2], bl[3]);
        }
    };

    float acc[2][8][4];
#pragma unroll
    for (int mt = 0; mt < 2; mt++)
#pragma unroll
        for (int nt = 0; nt < 8; nt++)
#pragma unroll
            for (int j = 0; j < 4; j++) acc[mt][nt][j] = 0.f;

    // fragment address components (m16n8k16)
    const int m0w = (wid & 3) * 32;     // warp m offset
    const int n0w = (wid >> 2) * 64;    // warp n offset
    const int frow = lane >> 2;         // 0..7
    const int fk2 = (lane & 3) * 2;     // even k within 16

    // prologue: stage tile 0, store it
    stA0 = *(const float4*)Ap;        stA1 = *(const float4*)(Ap + 4);
    stB0 = *(const float4*)Bp;        stB1 = *(const float4*)(Bp + 4);
    if (USE_BN) __syncthreads();      // ssv/stv visible before store_tile uses them
    store_tile(0, 0);
    __syncthreads();

    for (int kt = 0; kt < nkt; kt++) {
        const int buf = kt & 1;
        if (kt + 1 < nkt) {
            const float* ap = Ap + (size_t)(kt + 1) * 16;
            const float* bp = Bp + (size_t)(kt + 1) * 16;
            stA0 = *(const float4*)ap;  stA1 = *(const float4*)(ap + 4);
            stB0 = *(const float4*)bp;  stB1 = *(const float4*)(bp + 4);
        }
        // ---- compute on buf ----
        const char* tAhi = tiles + (buf * 4 + 0) * TILE_SZ;
        const char* tAlo = tiles + (buf * 4 + 1) * TILE_SZ;
        const char* tBhi = tiles + (buf * 4 + 2) * TILE_SZ;
        const char* tBlo = tiles + (buf * 4 + 3) * TILE_SZ;

        uint32_t ah[2][4], al[2][4], bh[8][2], bl[8][2];
#pragma unroll
        for (int mt = 0; mt < 2; mt++) {
            uint32_t base = (uint32_t)((m0w + mt * 16 + frow) * 48 + fk2 * 2);
            ah[mt][0] = *(const uint32_t*)(tAhi + base);
            ah[mt][1] = *(const uint32_t*)(tAhi + base + 8 * 48);
            ah[mt][2] = *(const uint32_t*)(tAhi + base + 16);
            ah[mt][3] = *(const uint32_t*)(tAhi + base + 8 * 48 + 16);
            al[mt][0] = *(const uint32_t*)(tAlo + base);
            al[mt][1] = *(const uint32_t*)(tAlo + base + 8 * 48);
            al[mt][2] = *(const uint32_t*)(tAlo + base + 16);
            al[mt][3] = *(const uint32_t*)(tAlo + base + 8 * 48 + 16);
        }
#pragma unroll
        for (int nt = 0; nt < 8; nt++) {
            uint32_t base = (uint32_t)((n0w + nt * 8 + frow) * 48 + fk2 * 2);
            bh[nt][0] = *(const uint32_t*)(tBhi + base);
            bh[nt][1] = *(const uint32_t*)(tBhi + base + 16);
            bl[nt][0] = *(const uint32_t*)(tBlo + base);
            bl[nt][1] = *(const uint32_t*)(tBlo + base + 16);
        }
#pragma unroll
        for (int mt = 0; mt < 2; mt++)
#pragma unroll
            for (int nt = 0; nt < 8; nt++) {
                mma_bf16(acc[mt][nt], ah[mt], bh[nt]);
                mma_bf16(acc[mt][nt], ah[mt], bl[nt]);
                mma_bf16(acc[mt][nt], al[mt], bh[nt]);
            }
        // ---- store next tile ----
        if (kt + 1 < nkt) {
            __syncthreads();             // everyone done reading buf^1 (from kt-1)
            store_tile(buf ^ 1, kt + 1);
            __syncthreads();
        }
    }

    // epilogue: bias + relu, float2 stores
#pragma unroll
    for (int mt = 0; mt < 2; mt++) {
        int m = bm + m0w + mt * 16 + frow;
#pragma unroll
        for (int nt = 0; nt < 8; nt++) {
            int n = bn + n0w + nt * 8 + fk2;
            float bx = __ldg(&bias[n]), by = __ldg(&bias[n + 1]);
            float2 o0, o1;
            o0.x = fmaxf(acc[mt][nt][0] + bx, 0.f);
            o0.y = fmaxf(acc[mt][nt][1] + by, 0.f);
            o1.x = fmaxf(acc[mt][nt][2] + bx, 0.f);
            o1.y = fmaxf(acc[mt][nt][3] + by, 0.f);
            *(float2*)(C + (size_t)m * H_DIM + n) = o0;
            *(float2*)(C + (size_t)(m + 8) * H_DIM + n) = o1;
        }
    }
}

// ---------------- per-column sum / sumsq over h1 ----------------
__global__ void colstats(const float* __restrict__ h) {
    int col = (blockIdx.x << 7) | (threadIdx.x & 127);
    int r0 = blockIdx.y * 512;
    float s = 0.f, s2 = 0.f;
#pragma unroll 4
    for (int r = 0; r < 512; r++) {
        float v = h[(size_t)(r0 + r) * H_DIM + col];
        s += v;
        s2 = fmaf(v, v, s2);
    }
    atomicAdd(&g_colsum[col], s);
    atomicAdd(&g_colsumsq[col], s2);
}

// ---------------- BN scale/shift ----------------
__global__ void finalize_stats(const float* __restrict__ gamma, const float* __restrict__ beta) {
    int j = threadIdx.x;
    if (j < H_DIM) {
        float mu = g_colsum[j] * (1.f / (float)B_ROWS);
        float var = g_colsumsq[j] * (1.f / (float)B_ROWS) - mu * mu;
        float s = gamma[j] * (1.0f / sqrtf(var + BN_EPS));
        g_s[j] = s;
        g_t[j] = beta[j] - mu * s;
    }
}

// ---------------- GEMM3: out[B,10] = h2 @ W3^T + b3 (warp per row), exact fp32 ----------------
__global__ void gemm3(const float* __restrict__ h2, const float* __restrict__ W3,
                      const float* __restrict__ b3, float* __restrict__ out) {
    int gwarp = (blockIdx.x * blockDim.x + threadIdx.x) >> 5;
    int lane = threadIdx.x & 31;
    const float4* hv = (const float4*)(h2 + (size_t)gwarp * H_DIM);
    float acc[10];
#pragma unroll
    for (int j = 0; j < 10; j++) acc[j] = 0.f;
#pragma unroll
    for (int c4 = 0; c4 < 4; c4++) {
        int c = lane + 32 * c4;
        float4 h4 = hv[c];
        int k = c << 2;
#pragma unroll
        for (int j = 0; j < 10; j++) {
            float4 w4 = __ldg((const float4*)(W3 + j * H_DIM + k));
            float a = fmaf(h4.x, w4.x, 0.f);
            a = fmaf(h4.y, w4.y, a);
            a = fmaf(h4.z, w4.z, a);
            a = fmaf(h4.w, w4.w, a);
            acc[j] += a;
        }
    }
#pragma unroll
    for (int j = 0; j < 10; j++)
#pragma unroll
        for (int off = 16; off; off >>= 1)
            acc[j] += __shfl_down_sync(0xffffffffu, acc[j], off);
    if (lane == 0) {
#pragma unroll
        for (int j = 0; j < 10; j++)
            out[(size_t)gwarp * D_OUT + j] = acc[j] + __ldg(&b3[j]);
    }
}

// ---------------- diff scalar ----------------
__global__ void write_diff(float* __restrict__ out, int out_size) {
    if (out_size > B_ROWS * D_OUT)
        out[out_size - 1] = g_diff1 * (1.f / (float)(H_DIM * D_IN)) +
                            g_diff2 * (1.f / (float)(H_DIM * H_DIM));
}

// ---------------- launcher ----------------
extern "C" void kernel_launch(void* const* d_in, const int* in_sizes, int n_in,
                              void* d_out, int out_size) {
    const float* x      = (const float*)d_in[0];
    const float* W1     = (const float*)d_in[1];
    const float* b1     = (const float*)d_in[2];
    const float* gamma1 = (const float*)d_in[3];
    const float* beta1  = (const float*)d_in[4];
    const float* E1     = (const float*)d_in[5];
    const float* W2     = (const float*)d_in[6];
    const float* b2     = (const float*)d_in[7];
    const float* E2     = (const float*)d_in[8];
    const float* W3     = (const float*)d_in[9];
    const float* b3     = (const float*)d_in[10];
    float* out = (float*)d_out;

    (void)in_sizes; (void)n_in;

    cudaFuncSetAttribute(quant_w1, cudaFuncAttributeMaxDynamicSharedMemorySize, 59392);
    cudaFuncSetAttribute(mma_gemm_relu<0>, cudaFuncAttributeMaxDynamicSharedMemorySize, GSMEM);
    cudaFuncSetAttribute(mma_gemm_relu<1>, cudaFuncAttributeMaxDynamicSharedMemorySize, GSMEM);

    float *qW1p, *qW2p, *h1p, *h2p, *sp, *tp;
    cudaGetSymbolAddress((void**)&qW1p, g_qW1);
    cudaGetSymbolAddress((void**)&qW2p, g_qW2);
    cudaGetSymbolAddress((void**)&h1p, g_h1);
    cudaGetSymbolAddress((void**)&h2p, g_h2);
    cudaGetSymbolAddress((void**)&sp, g_s);
    cudaGetSymbolAddress((void**)&tp, g_t);

    zero_accums<<<1, 512>>>();
    quant_w1<<<448, 128, (KCODE * 28 + KCODE) * sizeof(float)>>>(W1, E1);
    quant_w2<<<512, 128>>>(W2, E2);

    // h1 = relu(x @ qW1^T + b1)   [bf16x3 tensor-core]
    mma_gemm_relu<0><<<dim3(H_DIM / 128, B_ROWS / 128), 256, GSMEM>>>(
        x, qW1p, b1, h1p, nullptr, nullptr, D_IN);

    colstats<<<dim3(H_DIM / 128, B_ROWS / 512), 128>>>(h1p);
    finalize_stats<<<1, 512>>>(gamma1, beta1);

    // h2 = relu(bn(h1) @ qW2^T + b2)  — BN applied on the A-load path  [bf16x3]
    mma_gemm_relu<1><<<dim3(H_DIM / 128, B_ROWS / 128), 256, GSMEM>>>(
        h1p, qW2p, b2, h2p, sp, tp, H_DIM);

    // out = h2 @ W3^T + b3
    gemm3<<<B_ROWS / 8, 256>>>(h2p, W3, b3, out);

    write_diff<<<1, 1>>>(out, out_size);
}

// round 6
// speedup vs baseline: 2.1912x; 1.1636x over previous
#include <cuda_runtime.h>
#include <cuda_bf16.h>
#include <cstdint>
#include <math.h>

// Problem dims (fixed by the dataset)
#define B_ROWS 65536
#define D_IN   784
#define H_DIM  512
#define D_OUT  10
#define KCODE  512
#define BN_EPS 1e-5f

// ---------------- scratch (static device globals; no allocations) ----------------
__device__ float g_qW1[H_DIM * D_IN];
__device__ float g_qW2[H_DIM * H_DIM];
__device__ float g_h1[(size_t)B_ROWS * H_DIM];
__device__ float g_h2[(size_t)B_ROWS * H_DIM];
__device__ float g_colsum[H_DIM];
__device__ float g_colsumsq[H_DIM];
__device__ float g_s[H_DIM];
__device__ float g_t[H_DIM];
__device__ float g_diff1;
__device__ float g_diff2;

// ---------------- zero accumulators ----------------
__global__ void zero_accums() {
    int t = threadIdx.x;
    if (t < H_DIM) { g_colsum[t] = 0.f; g_colsumsq[t] = 0.f; }
    if (t == 0) { g_diff1 = 0.f; g_diff2 = 0.f; }
}

// Reference-replicating fp32 helpers (no contraction allowed)
__device__ __forceinline__ float sq_sum_seq(const float* v, int n) {
    float s = __fmul_rn(v[0], v[0]);
    for (int d = 1; d < n; d++) s = __fadd_rn(s, __fmul_rn(v[d], v[d]));
    return s;
}

// ---------------- VQ quantize W1 (unchanged from passing R3/R5) ----------------
__global__ void quant_w1(const float* __restrict__ W1, const float* __restrict__ E1) {
    extern __shared__ float smemq[];
    float* sE  = smemq;
    float* sSe = smemq + KCODE * 28;

    for (int i = threadIdx.x; i < KCODE * 28; i += 128) {
        int k = i / 28, d = i % 28;
        sE[k * 28 + d] = E1[d * KCODE + k];
    }
    __syncthreads();
    for (int k = threadIdx.x; k < KCODE; k += 128)
        sSe[k] = sq_sum_seq(sE + k * 28, 28);
    __syncthreads();

    int gid = blockIdx.x * 128 + threadIdx.x;
    int blk = gid >> 2;
    int sub = gid & 3;
    int og = blk / 112;
    int ig = blk - og * 112;

    float v[28];
#pragma unroll
    for (int im = 0; im < 7; im++)
#pragma unroll
        for (int om = 0; om < 4; om++)
            v[im * 4 + om] = W1[(og * 4 + om) * D_IN + ig * 7 + im];
    float Sv = sq_sum_seq(v, 28);

    float best = 3.402823e38f;
    int bi = 0x7fffffff;
    for (int i = 0; i < 128; i++) {
        int k = (i << 2) | sub;
        const float* e = sE + k * 28;
        float dot = 0.f;
#pragma unroll
        for (int d = 0; d < 28; d++) dot = __fmaf_rn(v[d], e[d], dot);
        float dist = __fadd_rn(__fsub_rn(Sv, __fmul_rn(2.0f, dot)), sSe[k]);
        if (dist < best) { best = dist; bi = k; }
    }
#pragma unroll
    for (int off = 2; off >= 1; off >>= 1) {
        float ob = __shfl_down_sync(0xffffffffu, best, off);
        int   oi = __shfl_down_sync(0xffffffffu, bi, off);
        if (ob < best || (ob == best && oi < bi)) { best = ob; bi = oi; }
    }
    if (sub == 0) {
        const float* e = sE + bi * 28;
        float dsum = 0.f;
#pragma unroll
        for (int im = 0; im < 7; im++)
#pragma unroll
            for (int om = 0; om < 4; om++) {
                int d = im * 4 + om;
                float q = e[d];
                g_qW1[(og * 4 + om) * D_IN + ig * 7 + im] = q;
                float df = q - v[d];
                dsum = fmaf(df, df, dsum);
            }
        atomicAdd(&g_diff1, dsum);
    }
}

// ---------------- VQ quantize W2 (unchanged from passing R3/R5) ----------------
__global__ void quant_w2(const float* __restrict__ W2, const float* __restrict__ E2) {
    __shared__ float sE[KCODE * 17];
    __shared__ float sSe[KCODE];
    for (int i = threadIdx.x; i < KCODE * 16; i += 128) {
        int k = i >> 4, d = i & 15;
        sE[k * 17 + d] = E2[d * KCODE + k];
    }
    __syncthreads();
    for (int k = threadIdx.x; k < KCODE; k += 128) {
        const float* e = sE + k * 17;
        float s = __fmul_rn(e[0], e[0]);
        for (int d = 1; d < 16; d++) s = __fadd_rn(s, __fmul_rn(e[d], e[d]));
        sSe[k] = s;
    }
    __syncthreads();

    int gid = blockIdx.x * 128 + threadIdx.x;
    int blk = gid >> 2;
    int sub = gid & 3;
    int og = blk >> 5;
    int ig = blk & 31;

    float v[16];
    const float4* wp = (const float4*)(W2 + og * H_DIM + ig * 16);
#pragma unroll
    for (int q4 = 0; q4 < 4; q4++) {
        float4 w = wp[q4];
        v[q4 * 4 + 0] = w.x; v[q4 * 4 + 1] = w.y; v[q4 * 4 + 2] = w.z; v[q4 * 4 + 3] = w.w;
    }
    float Sv = sq_sum_seq(v, 16);

    float best = 3.402823e38f;
    int bi = 0x7fffffff;
    for (int i = 0; i < 128; i++) {
        int k = (i << 2) | sub;
        const float* e = sE + k * 17;
        float dot = 0.f;
#pragma unroll
        for (int d = 0; d < 16; d++) dot = __fmaf_rn(v[d], e[d], dot);
        float dist = __fadd_rn(__fsub_rn(Sv, __fmul_rn(2.0f, dot)), sSe[k]);
        if (dist < best) { best = dist; bi = k; }
    }
#pragma unroll
    for (int off = 2; off >= 1; off >>= 1) {
        float ob = __shfl_down_sync(0xffffffffu, best, off);
        int   oi = __shfl_down_sync(0xffffffffu, bi, off);
        if (ob < best || (ob == best && oi < bi)) { best = ob; bi = oi; }
    }
    if (sub == 0) {
        const float* e = sE + bi * 17;
        float dsum = 0.f;
#pragma unroll
        for (int d = 0; d < 16; d++) {
            float q = e[d];
            g_qW2[og * H_DIM + ig * 16 + d] = q;
            float df = q - v[d];
            dsum = fmaf(df, df, dsum);
        }
        atomicAdd(&g_diff2, dsum);
    }
}

// ---------------- bf16x3 tensor-core GEMM via mma.sync + ldmatrix ----------------
// C[M,512] = relu(f(A)[M,K] @ B[512,K]^T + bias), f(A)=fma(A,s,t) if USE_BN.
// 128x128 CTA tile, BK=16, 8 warps (warp tile 32x64), hi/lo bf16 split, 3 HMMA passes.
// One barrier per k-tile: prefetch -> barrier -> ldmatrix -> MMA -> convert/store(next).
#define TILE_SZ   6144         // 128 rows * 48 bytes (16 halves + 16B pad)
#define SM_TILES0 4096         // after sv/tv vectors
#define GSMEM     (SM_TILES0 + 8 * TILE_SZ)   // 53248

__device__ __forceinline__ uint32_t pack_bf16(float lo_elem, float hi_elem) {
    __nv_bfloat162 h = __floats2bfloat162_rn(lo_elem, hi_elem);
    return *(uint32_t*)&h;
}
__device__ __forceinline__ uint32_t smem_u32(const void* p) {
    uint32_t a;
    asm("{ .reg .u64 t; cvta.to.shared.u64 t, %1; cvt.u32.u64 %0, t; }" : "=r"(a) : "l"(p));
    return a;
}
__device__ __forceinline__ void ldsm_x4(uint32_t* r, uint32_t addr) {
    asm volatile("ldmatrix.sync.aligned.m8n8.x4.shared.b16 {%0,%1,%2,%3}, [%4];"
                 : "=r"(r[0]), "=r"(r[1]), "=r"(r[2]), "=r"(r[3]) : "r"(addr));
}
__device__ __forceinline__ void mma_bf16(float* d, const uint32_t* a, const uint32_t* b) {
    asm volatile(
        "mma.sync.aligned.m16n8k16.row.col.f32.bf16.bf16.f32 "
        "{%0,%1,%2,%3}, {%4,%5,%6,%7}, {%8,%9}, {%0,%1,%2,%3};"
        : "+f"(d[0]), "+f"(d[1]), "+f"(d[2]), "+f"(d[3])
        : "r"(a[0]), "r"(a[1]), "r"(a[2]), "r"(a[3]), "r"(b[0]), "r"(b[1]));
}

template <int USE_BN, int COLSTATS>
__global__ __launch_bounds__(256, 2) void mma_gemm_relu(
    const float* __restrict__ A, const float* __restrict__ Bmat,
    const float* __restrict__ bias, float* __restrict__ C,
    const float* __restrict__ sv, const float* __restrict__ tv, int K)
{
    extern __shared__ char sm[];
    float* ssv = (float*)sm;
    float* stv = ssv + 512;
    char* tiles = sm + SM_TILES0;
    const uint32_t tiles_u = smem_u32(tiles);

    const int tid = threadIdx.x;
    const int wid = tid >> 5, lane = tid & 31;
    const int bm = blockIdx.y * 128;
    const int bn = blockIdx.x * 128;

    if (USE_BN) {
        for (int i = tid; i < H_DIM; i += 256) { ssv[i] = sv[i]; stv[i] = tv[i]; }
    }

    // gmem staging: thread loads 8 consecutive floats of one row (A and B)
    const int row = tid >> 1;            // 0..127
    const int colbase = (tid & 1) * 8;   // 0 or 8
    const float* Ap = A + (size_t)(bm + row) * K + colbase;
    const float* Bp = Bmat + (size_t)(bn + row) * K + colbase;

    float4 stA0, stA1, stB0, stB1;
    const int nkt = K / 16;

    auto store_tile = [&](int buf, int kt) {
        char* tAhi = tiles + (buf * 4 + 0) * TILE_SZ;
        char* tAlo = tiles + (buf * 4 + 1) * TILE_SZ;
        char* tBhi = tiles + (buf * 4 + 2) * TILE_SZ;
        char* tBlo = tiles + (buf * 4 + 3) * TILE_SZ;
        float a[8] = {stA0.x, stA0.y, stA0.z, stA0.w, stA1.x, stA1.y, stA1.z, stA1.w};
        float b[8] = {stB0.x, stB0.y, stB0.z, stB0.w, stB1.x, stB1.y, stB1.z, stB1.w};
        if (USE_BN) {
            int gk = kt * 16 + colbase;
#pragma unroll
            for (int j = 0; j < 8; j++) a[j] = __fmaf_rn(a[j], ssv[gk + j], stv[gk + j]);
        }
        float ah[8], al[8], bh[8], bl[8];
#pragma unroll
        for (int j = 0; j < 8; j++) {
            float fh = __bfloat162float(__float2bfloat16_rn(a[j]));
            ah[j] = fh; al[j] = __fsub_rn(a[j], fh);
            fh = __bfloat162float(__float2bfloat16_rn(b[j]));
            bh[j] = fh; bl[j] = __fsub_rn(b[j], fh);
        }
        uint32_t off = (uint32_t)(row * 48 + colbase * 2);
        *(uint4*)(tAhi + off) = make_uint4(pack_bf16(ah[0], ah[1]), pack_bf16(ah[2], ah[3]),
                                           pack_bf16(ah[4], ah[5]), pack_bf16(ah[6], ah[7]));
        *(uint4*)(tAlo + off) = make_uint4(pack_bf16(al[0], al[1]), pack_bf16(al[2], al[3]),
                                           pack_bf16(al[4], al[5]), pack_bf16(al[6], al[7]));
        *(uint4*)(tBhi + off) = make_uint4(pack_bf16(bh[0], bh[1]), pack_bf16(bh[2], bh[3]),
                                           pack_bf16(bh[4], bh[5]), pack_bf16(bh[6], bh[7]));
        *(uint4*)(tBlo + off) = make_uint4(pack_bf16(bl[0], bl[1]), pack_bf16(bl[2], bl[3]),
                                           pack_bf16(bl[4], bl[5]), pack_bf16(bl[6], bl[7]));
    };

    float acc[2][8][4];
#pragma unroll
    for (int mt = 0; mt < 2; mt++)
#pragma unroll
        for (int nt = 0; nt < 8; nt++)
#pragma unroll
            for (int j = 0; j < 4; j++) acc[mt][nt][j] = 0.f;

    const int m0w = (wid & 3) * 32;
    const int n0w = (wid >> 2) * 64;
    const int frow = lane >> 2;
    const int fk2 = (lane & 3) * 2;

    // ldmatrix per-thread address components
    const uint32_t arow = (uint32_t)((lane & 7) + ((lane >> 3) & 1) * 8);   // A: row-in-16, matrices 0/1 by seg0, 2/3 seg1
    const uint32_t aseg = (uint32_t)(((lane >> 4) & 1) * 16);
    const uint32_t brow = (uint32_t)(((lane >> 4) & 1) * 8 + (lane & 7));   // B: matrices (nt,seg0),(nt,seg1),(nt+1,seg0),(nt+1,seg1)
    const uint32_t bseg = (uint32_t)(((lane >> 3) & 1) * 16);

    // prologue: stage tile 0, store it
    stA0 = *(const float4*)Ap;        stA1 = *(const float4*)(Ap + 4);
    stB0 = *(const float4*)Bp;        stB1 = *(const float4*)(Bp + 4);
    if (USE_BN) __syncthreads();
    store_tile(0, 0);

    for (int kt = 0; kt < nkt; kt++) {
        const int buf = kt & 1;
        if (kt + 1 < nkt) {
            const float* ap = Ap + (size_t)(kt + 1) * 16;
            const float* bp = Bp + (size_t)(kt + 1) * 16;
            stA0 = *(const float4*)ap;  stA1 = *(const float4*)(ap + 4);
            stB0 = *(const float4*)bp;  stB1 = *(const float4*)(bp + 4);
        }
        __syncthreads();   // previous store (buf) visible; all warps done reading buf^1

        const uint32_t tAhi = tiles_u + (buf * 4 + 0) * TILE_SZ;
        const uint32_t tAlo = tiles_u + (buf * 4 + 1) * TILE_SZ;
        const uint32_t tBhi = tiles_u + (buf * 4 + 2) * TILE_SZ;
        const uint32_t tBlo = tiles_u + (buf * 4 + 3) * TILE_SZ;

        uint32_t ah[2][4], al[2][4];
#pragma unroll
        for (int mt = 0; mt < 2; mt++) {
            uint32_t ao = (uint32_t)((m0w + mt * 16 + arow) * 48) + aseg;
            ldsm_x4(ah[mt], tAhi + ao);
            ldsm_x4(al[mt], tAlo + ao);
        }
#pragma unroll
        for (int ntp = 0; ntp < 4; ntp++) {
            uint32_t bo = (uint32_t)((n0w + ntp * 16 + brow) * 48) + bseg;
            uint32_t bh[4], bl[4];
            ldsm_x4(bh, tBhi + bo);
            ldsm_x4(bl, tBlo + bo);
#pragma unroll
            for (int h = 0; h < 2; h++) {
                int nt = ntp * 2 + h;
#pragma unroll
                for (int mt = 0; mt < 2; mt++) {
                    mma_bf16(acc[mt][nt], ah[mt], bh + h * 2);
                    mma_bf16(acc[mt][nt], ah[mt], bl + h * 2);
                    mma_bf16(acc[mt][nt], al[mt], bh + h * 2);
                }
            }
        }
        // convert+store next tile while tensor pipe drains
        if (kt + 1 < nkt) store_tile(buf ^ 1, kt + 1);
    }

    // epilogue: bias + relu, float2 stores (+ fused column stats for layer 1)
    float cs[8][2], cs2[8][2];
    if (COLSTATS) {
#pragma unroll
        for (int nt = 0; nt < 8; nt++) { cs[nt][0] = cs[nt][1] = 0.f; cs2[nt][0] = cs2[nt][1] = 0.f; }
    }
#pragma unroll
    for (int mt = 0; mt < 2; mt++) {
        int m = bm + m0w + mt * 16 + frow;
#pragma unroll
        for (int nt = 0; nt < 8; nt++) {
            int n = bn + n0w + nt * 8 + fk2;
            float bx = __ldg(&bias[n]), by = __ldg(&bias[n + 1]);
            float o0 = fmaxf(acc[mt][nt][0] + bx, 0.f);
            float o1 = fmaxf(acc[mt][nt][1] + by, 0.f);
            float o2 = fmaxf(acc[mt][nt][2] + bx, 0.f);
            float o3 = fmaxf(acc[mt][nt][3] + by, 0.f);
            *(float2*)(C + (size_t)m * H_DIM + n) = make_float2(o0, o1);
            *(float2*)(C + (size_t)(m + 8) * H_DIM + n) = make_float2(o2, o3);
            if (COLSTATS) {
                cs[nt][0] += o0 + o2;   cs[nt][1] += o1 + o3;
                cs2[nt][0] = fmaf(o0, o0, fmaf(o2, o2, cs2[nt][0]));
                cs2[nt][1] = fmaf(o1, o1, fmaf(o3, o3, cs2[nt][1]));
            }
        }
    }
    if (COLSTATS) {
#pragma unroll
        for (int off = 4; off <= 16; off <<= 1)
#pragma unroll
            for (int nt = 0; nt < 8; nt++)
#pragma unroll
                for (int j = 0; j < 2; j++) {
                    cs[nt][j]  += __shfl_down_sync(0xffffffffu, cs[nt][j], off);
                    cs2[nt][j] += __shfl_down_sync(0xffffffffu, cs2[nt][j], off);
                }
        if (lane < 4) {
#pragma unroll
            for (int nt = 0; nt < 8; nt++)
#pragma unroll
                for (int j = 0; j < 2; j++) {
                    int n = bn + n0w + nt * 8 + lane * 2 + j;
                    atomicAdd(&g_colsum[n], cs[nt][j]);
                    atomicAdd(&g_colsumsq[n], cs2[nt][j]);
                }
        }
    }
}

// ---------------- BN scale/shift ----------------
__global__ void finalize_stats(const float* __restrict__ gamma, const float* __restrict__ beta) {
    int j = threadIdx.x;
    if (j < H_DIM) {
        float mu = g_colsum[j] * (1.f / (float)B_ROWS);
        float var = g_colsumsq[j] * (1.f / (float)B_ROWS) - mu * mu;
        float s = gamma[j] * (1.0f / sqrtf(var + BN_EPS));
        g_s[j] = s;
        g_t[j] = beta[j] - mu * s;
    }
}

// ---------------- GEMM3: out[B,10] = h2 @ W3^T + b3 (warp per row), exact fp32 ----------------
__global__ void gemm3(const float* __restrict__ h2, const float* __restrict__ W3,
                      const float* __restrict__ b3, float* __restrict__ out) {
    int gwarp = (blockIdx.x * blockDim.x + threadIdx.x) >> 5;
    int lane = threadIdx.x & 31;
    const float4* hv = (const float4*)(h2 + (size_t)gwarp * H_DIM);
    float acc[10];
#pragma unroll
    for (int j = 0; j < 10; j++) acc[j] = 0.f;
#pragma unroll
    for (int c4 = 0; c4 < 4; c4++) {
        int c = lane + 32 * c4;
        float4 h4 = hv[c];
        int k = c << 2;
#pragma unroll
        for (int j = 0; j < 10; j++) {
            float4 w4 = __ldg((const float4*)(W3 + j * H_DIM + k));
            float a = fmaf(h4.x, w4.x, 0.f);
            a = fmaf(h4.y, w4.y, a);
            a = fmaf(h4.z, w4.z, a);
            a = fmaf(h4.w, w4.w, a);
            acc[j] += a;
        }
    }
#pragma unroll
    for (int j = 0; j < 10; j++)
#pragma unroll
        for (int off = 16; off; off >>= 1)
            acc[j] += __shfl_down_sync(0xffffffffu, acc[j], off);
    if (lane == 0) {
#pragma unroll
        for (int j = 0; j < 10; j++)
            out[(size_t)gwarp * D_OUT + j] = acc[j] + __ldg(&b3[j]);
    }
}

// ---------------- diff scalar ----------------
__global__ void write_diff(float* __restrict__ out, int out_size) {
    if (out_size > B_ROWS * D_OUT)
        out[out_size - 1] = g_diff1 * (1.f / (float)(H_DIM * D_IN)) +
                            g_diff2 * (1.f / (float)(H_DIM * H_DIM));
}

// ---------------- launcher ----------------
extern "C" void kernel_launch(void* const* d_in, const int* in_sizes, int n_in,
                              void* d_out, int out_size) {
    const float* x      = (const float*)d_in[0];
    const float* W1     = (const float*)d_in[1];
    const float* b1     = (const float*)d_in[2];
    const float* gamma1 = (const float*)d_in[3];
    const float* beta1  = (const float*)d_in[4];
    const float* E1     = (const float*)d_in[5];
    const float* W2     = (const float*)d_in[6];
    const float* b2     = (const float*)d_in[7];
    const float* E2     = (const float*)d_in[8];
    const float* W3     = (const float*)d_in[9];
    const float* b3     = (const float*)d_in[10];
    float* out = (float*)d_out;

    (void)in_sizes; (void)n_in;

    cudaFuncSetAttribute(quant_w1, cudaFuncAttributeMaxDynamicSharedMemorySize, 59392);
    cudaFuncSetAttribute((const void*)&mma_gemm_relu<0, 1>, cudaFuncAttributeMaxDynamicSharedMemorySize, GSMEM);
    cudaFuncSetAttribute((const void*)&mma_gemm_relu<1, 0>, cudaFuncAttributeMaxDynamicSharedMemorySize, GSMEM);

    float *qW1p, *qW2p, *h1p, *h2p, *sp, *tp;
    cudaGetSymbolAddress((void**)&qW1p, g_qW1);
    cudaGetSymbolAddress((void**)&qW2p, g_qW2);
    cudaGetSymbolAddress((void**)&h1p, g_h1);
    cudaGetSymbolAddress((void**)&h2p, g_h2);
    cudaGetSymbolAddress((void**)&sp, g_s);
    cudaGetSymbolAddress((void**)&tp, g_t);

    zero_accums<<<1, 512>>>();
    quant_w1<<<448, 128, (KCODE * 28 + KCODE) * sizeof(float)>>>(W1, E1);
    quant_w2<<<512, 128>>>(W2, E2);

    // h1 = relu(x @ qW1^T + b1)   [bf16x3 tensor-core, fused column stats]
    mma_gemm_relu<0, 1><<<dim3(H_DIM / 128, B_ROWS / 128), 256, GSMEM>>>(
        x, qW1p, b1, h1p, nullptr, nullptr, D_IN);

    finalize_stats<<<1, 512>>>(gamma1, beta1);

    // h2 = relu(bn(h1) @ qW2^T + b2)  — BN applied on the A-load path  [bf16x3]
    mma_gemm_relu<1, 0><<<dim3(H_DIM / 128, B_ROWS / 128), 256, GSMEM>>>(
        h1p, qW2p, b2, h2p, sp, tp, H_DIM);

    // out = h2 @ W3^T + b3
    gemm3<<<B_ROWS / 8, 256>>>(h2p, W3, b3, out);

    write_diff<<<1, 1>>>(out, out_size);
}